// round 4
// baseline (speedup 1.0000x reference)
#include <cuda_runtime.h>
#include <math_constants.h>

#define NROI 2048
#define CDIM 1024
#define GRP  16
#define DH   64

// ---- device scratch (no allocations allowed) ----
__device__ float g_H0[NROI * CDIM];   // embed layer-0 output
__device__ float g_X [NROI * CDIM];   // embedded features X
__device__ float g_P [NROI * CDIM];   // P = in_x @ Wout_flat^T  (values, pre-projected)
__device__ float g_LI[NROI * NROI];   // log(iou + 1e-6)

// ============================================================================
// SGEMM: C = act(A) @ W^T + bias
//   A (M,K) row-major, W (Nout,K) row-major, C (M,Nout) row-major
//   BM=128, BN=64, BK=16, 256 threads, 8x4 per thread
// ============================================================================
template<bool RELU>
__global__ __launch_bounds__(256)
void sgemm_bias(const float* __restrict__ A, const float* __restrict__ W,
                const float* __restrict__ bias, float* __restrict__ C,
                int M, int Nout, int K) {
    constexpr int BM = 128, BN = 64, BK = 16;
    __shared__ float As[BK][BM];
    __shared__ float Bs[BK][BN];

    const int tid = threadIdx.x;
    const int tx = tid & 15;        // 0..15 -> N cols (x4)
    const int ty = tid >> 4;        // 0..15 -> M rows (x8)
    const int row0 = blockIdx.y * BM;
    const int col0 = blockIdx.x * BN;

    float acc[8][4] = {};

    for (int kb = 0; kb < K; kb += BK) {
        // load A tile: 128x16 = 512 float4, 2 per thread
        #pragma unroll
        for (int u = 0; u < 2; u++) {
            int id = tid + u * 256;
            int r  = id >> 2;
            int k0 = (id & 3) << 2;
            float4 v = *(const float4*)(A + (size_t)(row0 + r) * K + kb + k0);
            if (RELU) {
                v.x = fmaxf(v.x, 0.f); v.y = fmaxf(v.y, 0.f);
                v.z = fmaxf(v.z, 0.f); v.w = fmaxf(v.w, 0.f);
            }
            As[k0 + 0][r] = v.x; As[k0 + 1][r] = v.y;
            As[k0 + 2][r] = v.z; As[k0 + 3][r] = v.w;
        }
        // load W tile: 64x16 = 256 float4, 1 per thread
        {
            int r  = tid >> 2;
            int k0 = (tid & 3) << 2;
            float4 v = *(const float4*)(W + (size_t)(col0 + r) * K + kb + k0);
            Bs[k0 + 0][r] = v.x; Bs[k0 + 1][r] = v.y;
            Bs[k0 + 2][r] = v.z; Bs[k0 + 3][r] = v.w;
        }
        __syncthreads();

        #pragma unroll
        for (int k = 0; k < BK; k++) {
            float4 a0 = *(const float4*)&As[k][ty * 8];
            float4 a1 = *(const float4*)&As[k][ty * 8 + 4];
            float4 b  = *(const float4*)&Bs[k][tx * 4];
            float ar[8] = {a0.x, a0.y, a0.z, a0.w, a1.x, a1.y, a1.z, a1.w};
            float br[4] = {b.x, b.y, b.z, b.w};
            #pragma unroll
            for (int i = 0; i < 8; i++)
                #pragma unroll
                for (int j = 0; j < 4; j++)
                    acc[i][j] = fmaf(ar[i], br[j], acc[i][j]);
        }
        __syncthreads();
    }

    float4 bv = make_float4(0.f, 0.f, 0.f, 0.f);
    if (bias) bv = *(const float4*)(bias + col0 + tx * 4);
    #pragma unroll
    for (int i = 0; i < 8; i++) {
        float4 o = make_float4(acc[i][0] + bv.x, acc[i][1] + bv.y,
                               acc[i][2] + bv.z, acc[i][3] + bv.w);
        *(float4*)(C + (size_t)(row0 + ty * 8 + i) * Nout + col0 + tx * 4) = o;
    }
}

// ============================================================================
// log(IoU + 1e-6) table, mmdet +1 pixel convention
// ============================================================================
__global__ __launch_bounds__(256)
void logiou_kernel(const float* __restrict__ rois, float* __restrict__ li) {
    int idx = blockIdx.x * blockDim.x + threadIdx.x;
    int n = idx >> 11;       // / 2048
    int m = idx & 2047;
    const float* a = rois + n * 5 + 1;
    const float* b = rois + m * 5 + 1;
    float ax1 = a[0], ay1 = a[1], ax2 = a[2], ay2 = a[3];
    float bx1 = b[0], by1 = b[1], bx2 = b[2], by2 = b[3];
    float areaA = (ax2 - ax1 + 1.f) * (ay2 - ay1 + 1.f);
    float areaB = (bx2 - bx1 + 1.f) * (by2 - by1 + 1.f);
    float w = fminf(ax2, bx2) - fmaxf(ax1, bx1) + 1.f; w = fmaxf(w, 0.f);
    float h = fminf(ay2, by2) - fmaxf(ay1, by1) + 1.f; h = fmaxf(h, 0.f);
    float inter = w * h;
    float iou = inter / (areaA + areaB - inter);
    li[idx] = logf(iou + 1e-6f);
}

// ============================================================================
// Fused attention (flash-style):
//   out[n, g*64 + o] = softmax_m( X_g[n]·X_g[m]/8 + LI[n,m] ) · P[m, g*64 + o]
//                      + bout[g*64 + o]
// Tiles: BQ=64 query rows, BKV=64 key rows, head dim 64.
// 256 threads, each owns a 4x4 tile of S and of O.
// Smem layouts (stride 68 keeps float4 alignment, 2-way max conflicts):
//   Qs[d][r]  (transposed, pre-scaled by 1/8)
//   Ks[d][m]  (transposed)
//   Vs[m][d]  (row-major; V = P slice)
//   Ps[r][m]  (row-major probabilities)
// ============================================================================
__global__ __launch_bounds__(256)
void flash_kernel(const float* __restrict__ X, const float* __restrict__ P,
                  const float* __restrict__ LI, const float* __restrict__ bout,
                  float* __restrict__ out) {
    constexpr int LDS = 68;
    extern __shared__ float sm[];
    float* Qs = sm;                  // 64*68
    float* Ks = Qs + 64 * LDS;
    float* Vs = Ks + 64 * LDS;
    float* Ps = Vs + 64 * LDS;

    const int g  = blockIdx.y;
    const int n0 = blockIdx.x * 64;
    const int tid = threadIdx.x;
    const int tx = tid & 15;
    const int ty = tid >> 4;
    const int r0 = ty * 4;           // S/O row base within tile
    const int c0 = tx * 4;           // S col (key) / O col (out-dim) base

    // ---- load Q transposed, scaled by 1/sqrt(64) ----
    for (int i = tid; i < 64 * 16; i += 256) {
        int r  = i >> 4;
        int d0 = (i & 15) << 2;
        float4 v = *(const float4*)(X + (size_t)(n0 + r) * CDIM + g * DH + d0);
        Qs[(d0 + 0) * LDS + r] = v.x * 0.125f;
        Qs[(d0 + 1) * LDS + r] = v.y * 0.125f;
        Qs[(d0 + 2) * LDS + r] = v.z * 0.125f;
        Qs[(d0 + 3) * LDS + r] = v.w * 0.125f;
    }

    float m_i[4], l_i[4], O[4][4];
    #pragma unroll
    for (int r = 0; r < 4; r++) {
        m_i[r] = -CUDART_INF_F;
        l_i[r] = 0.f;
        #pragma unroll
        for (int c = 0; c < 4; c++) O[r][c] = 0.f;
    }

    for (int m0 = 0; m0 < NROI; m0 += 64) {
        __syncthreads();   // prior iter's reads of Ks/Vs/Ps done
        // ---- load K (transposed) and V (row-major) ----
        for (int i = tid; i < 64 * 16; i += 256) {
            int r  = i >> 4;
            int d0 = (i & 15) << 2;
            float4 kv = *(const float4*)(X + (size_t)(m0 + r) * CDIM + g * DH + d0);
            Ks[(d0 + 0) * LDS + r] = kv.x;
            Ks[(d0 + 1) * LDS + r] = kv.y;
            Ks[(d0 + 2) * LDS + r] = kv.z;
            Ks[(d0 + 3) * LDS + r] = kv.w;
            float4 vv = *(const float4*)(P + (size_t)(m0 + r) * CDIM + g * DH + d0);
            *(float4*)&Vs[r * LDS + d0] = vv;
        }
        __syncthreads();

        // ---- S = Q K^T (Q already scaled) ----
        float S[4][4] = {};
        #pragma unroll 8
        for (int d = 0; d < 64; d++) {
            float4 q = *(const float4*)&Qs[d * LDS + r0];
            float4 k = *(const float4*)&Ks[d * LDS + c0];
            float qa[4] = {q.x, q.y, q.z, q.w};
            float ka[4] = {k.x, k.y, k.z, k.w};
            #pragma unroll
            for (int r = 0; r < 4; r++)
                #pragma unroll
                for (int c = 0; c < 4; c++)
                    S[r][c] = fmaf(qa[r], ka[c], S[r][c]);
        }
        // ---- add log-IoU bias ----
        #pragma unroll
        for (int r = 0; r < 4; r++) {
            float4 b = *(const float4*)(LI + (size_t)(n0 + r0 + r) * NROI + m0 + c0);
            S[r][0] += b.x; S[r][1] += b.y; S[r][2] += b.z; S[r][3] += b.w;
        }

        // ---- online softmax (row stats reduced over the 16 tx lanes) ----
        #pragma unroll
        for (int r = 0; r < 4; r++) {
            float mt = fmaxf(fmaxf(S[r][0], S[r][1]), fmaxf(S[r][2], S[r][3]));
            #pragma unroll
            for (int off = 8; off; off >>= 1)
                mt = fmaxf(mt, __shfl_xor_sync(0xffffffffu, mt, off));
            float mn = fmaxf(m_i[r], mt);
            float alpha = __expf(m_i[r] - mn);     // exp(-inf)=0 on first block
            m_i[r] = mn;
            float rs = 0.f;
            #pragma unroll
            for (int c = 0; c < 4; c++) {
                float p = __expf(S[r][c] - mn);
                Ps[(r0 + r) * LDS + c0 + c] = p;
                rs += p;
            }
            #pragma unroll
            for (int off = 8; off; off >>= 1)
                rs += __shfl_xor_sync(0xffffffffu, rs, off);
            l_i[r] = l_i[r] * alpha + rs;
            #pragma unroll
            for (int c = 0; c < 4; c++) O[r][c] *= alpha;
        }
        __syncthreads();   // Ps visible to all

        // ---- O += P_tile @ V_tile ----
        for (int m4 = 0; m4 < 64; m4 += 4) {
            float pr[4][4];
            #pragma unroll
            for (int r = 0; r < 4; r++) {
                float4 p4 = *(const float4*)&Ps[(r0 + r) * LDS + m4];
                pr[r][0] = p4.x; pr[r][1] = p4.y; pr[r][2] = p4.z; pr[r][3] = p4.w;
            }
            #pragma unroll
            for (int mm = 0; mm < 4; mm++) {
                float4 v = *(const float4*)&Vs[(m4 + mm) * LDS + c0];
                float va[4] = {v.x, v.y, v.z, v.w};
                #pragma unroll
                for (int r = 0; r < 4; r++)
                    #pragma unroll
                    for (int c = 0; c < 4; c++)
                        O[r][c] = fmaf(pr[r][mm], va[c], O[r][c]);
            }
        }
    }

    // ---- epilogue: normalize, add bout ----
    float4 bo = *(const float4*)(bout + g * DH + c0);
    #pragma unroll
    for (int r = 0; r < 4; r++) {
        float inv = 1.f / l_i[r];
        float4 o = make_float4(O[r][0] * inv + bo.x, O[r][1] * inv + bo.y,
                               O[r][2] * inv + bo.z, O[r][3] * inv + bo.w);
        *(float4*)(out + (size_t)(n0 + r0 + r) * CDIM + g * DH + c0) = o;
    }
}

// ============================================================================
// launch
// ============================================================================
extern "C" void kernel_launch(void* const* d_in, const int* in_sizes, int n_in,
                              void* d_out, int out_size) {
    const float* in_x = (const float*)d_in[0];
    const float* rois = (const float*)d_in[1];
    const float* W0   = (const float*)d_in[2];
    const float* b0   = (const float*)d_in[3];
    const float* W1   = (const float*)d_in[4];
    const float* b1   = (const float*)d_in[5];
    const float* Wout = (const float*)d_in[6];   // (G,D,C) == flat (C_out=1024, C)
    const float* bout = (const float*)d_in[7];
    float* out = (float*)d_out;

    void *pH0, *pX, *pP, *pLI;
    cudaGetSymbolAddress(&pH0, g_H0);
    cudaGetSymbolAddress(&pX,  g_X);
    cudaGetSymbolAddress(&pP,  g_P);
    cudaGetSymbolAddress(&pLI, g_LI);
    float* H0 = (float*)pH0;
    float* X  = (float*)pX;
    float* P  = (float*)pP;
    float* LI = (float*)pLI;

    dim3 ggrid(CDIM / 64, NROI / 128);   // 16 x 16 = 256 blocks

    // embed: x = relu(in_x)@W0^T + b0 ; x = relu(x)@W1^T + b1
    sgemm_bias<true ><<<ggrid, 256>>>(in_x, W0, b0, H0, NROI, CDIM, CDIM);
    sgemm_bias<true ><<<ggrid, 256>>>(H0,  W1, b1, X,  NROI, CDIM, CDIM);
    // P = in_x @ Wout_flat^T   (bout added in flash epilogue)
    sgemm_bias<false><<<ggrid, 256>>>(in_x, Wout, nullptr, P, NROI, CDIM, CDIM);
    // log(IoU + 1e-6)
    logiou_kernel<<<(NROI * NROI) / 256, 256>>>(rois, LI);

    // fused attention
    size_t smem = 4 * 64 * 68 * sizeof(float);   // 69632 B
    cudaFuncSetAttribute(flash_kernel,
                         cudaFuncAttributeMaxDynamicSharedMemorySize, (int)smem);
    flash_kernel<<<dim3(NROI / 64, GRP), 256, smem>>>(X, P, LI, bout, out);
}

// round 8
// speedup vs baseline: 1.3557x; 1.3557x over previous
#include <cuda_runtime.h>
#include <cuda_bf16.h>
#include <math_constants.h>
#include <cstdint>

#define NROI 2048
#define CDIM 1024
#define GRP  16
#define DH   64

// ============================================================================
// device scratch (static __device__ arrays: the sanctioned no-alloc path)
// ============================================================================
__device__ __nv_bfloat16 g_A0h[NROI * CDIM], g_A0l[NROI * CDIM];   // split relu(in_x)
__device__ __nv_bfloat16 g_A1h[NROI * CDIM], g_A1l[NROI * CDIM];   // split relu(H0)
__device__ __nv_bfloat16 g_A2h[NROI * CDIM], g_A2l[NROI * CDIM];   // split in_x
__device__ __nv_bfloat16 g_W0h[CDIM * CDIM], g_W0l[CDIM * CDIM];
__device__ __nv_bfloat16 g_W1h[CDIM * CDIM], g_W1l[CDIM * CDIM];
__device__ __nv_bfloat16 g_Wph[CDIM * CDIM], g_Wpl[CDIM * CDIM];
__device__ float g_X [NROI * CDIM];    // embedded features (flash Q/K)
__device__ float g_P [NROI * CDIM];    // P = in_x @ Wout^T (flash V)
__device__ float g_LI[NROI * NROI];    // log(iou + 1e-6)

// ============================================================================
// base-ISA PTX helpers (NO tcgen05 — harness PTX target is sm_103 plain)
// ============================================================================
__device__ __forceinline__ uint32_t smem_u32(const void* p) {
    uint32_t a;
    asm("{ .reg .u64 t; cvta.to.shared.u64 t, %1; cvt.u32.u64 %0, t; }" : "=r"(a) : "l"(p));
    return a;
}

#define LDSM4(r, addr) \
    asm volatile("ldmatrix.sync.aligned.m8n8.x4.shared.b16 {%0,%1,%2,%3}, [%4];" \
        : "=r"((r)[0]), "=r"((r)[1]), "=r"((r)[2]), "=r"((r)[3]) : "r"(addr))
#define LDSM2(r, addr) \
    asm volatile("ldmatrix.sync.aligned.m8n8.x2.shared.b16 {%0,%1}, [%2];" \
        : "=r"((r)[0]), "=r"((r)[1]) : "r"(addr))
#define MMA_BF16(c, a, b) \
    asm volatile("mma.sync.aligned.m16n8k16.row.col.f32.bf16.bf16.f32 " \
        "{%0,%1,%2,%3}, {%4,%5,%6,%7}, {%8,%9}, {%0,%1,%2,%3};" \
        : "+f"((c)[0]), "+f"((c)[1]), "+f"((c)[2]), "+f"((c)[3]) \
        : "r"((a)[0]), "r"((a)[1]), "r"((a)[2]), "r"((a)[3]), "r"((b)[0]), "r"((b)[1]))
#define CP16(dst, src)  asm volatile("cp.async.cg.shared.global [%0], [%1], 16;" :: "r"(dst), "l"(src))
#define CP_COMMIT()     asm volatile("cp.async.commit_group;" ::: "memory")
#define CP_WAIT(n)      asm volatile("cp.async.wait_group %0;" :: "n"(n) : "memory")

// packed f32x2 helpers (compiled fine under sm_103 in R6)
__device__ __forceinline__ uint64_t pk2(float lo, float hi) {
    uint64_t r; asm("mov.b64 %0, {%1, %2};" : "=l"(r) : "f"(lo), "f"(hi)); return r;
}
__device__ __forceinline__ void upk2(float& lo, float& hi, uint64_t v) {
    asm("mov.b64 {%0, %1}, %2;" : "=f"(lo), "=f"(hi) : "l"(v));
}
__device__ __forceinline__ void ffma2(uint64_t& d, uint64_t a, uint64_t b) {
    asm("fma.rn.f32x2 %0, %1, %2, %0;" : "+l"(d) : "l"(a), "l"(b));
}
__device__ __forceinline__ uint64_t mul2(uint64_t a, uint64_t b) {
    uint64_t r; asm("mul.rn.f32x2 %0, %1, %2;" : "=l"(r) : "l"(a), "l"(b)); return r;
}

// ============================================================================
// split kernel: fp32 -> (hi, lo) bf16, optional relu.  n4 = elements/4
// ============================================================================
__global__ __launch_bounds__(256)
void split_kernel(const float* __restrict__ in, __nv_bfloat16* __restrict__ hi,
                  __nv_bfloat16* __restrict__ lo, int n4, int relu) {
    int i = blockIdx.x * blockDim.x + threadIdx.x;
    if (i >= n4) return;
    float4 v = ((const float4*)in)[i];
    if (relu) {
        v.x = fmaxf(v.x, 0.f); v.y = fmaxf(v.y, 0.f);
        v.z = fmaxf(v.z, 0.f); v.w = fmaxf(v.w, 0.f);
    }
    float f[4] = {v.x, v.y, v.z, v.w};
    uint32_t hu[2], lu[2];
    #pragma unroll
    for (int j = 0; j < 2; j++) {
        __nv_bfloat16 h0 = __float2bfloat16(f[2*j]);
        __nv_bfloat16 h1 = __float2bfloat16(f[2*j+1]);
        __nv_bfloat16 l0 = __float2bfloat16(f[2*j]   - __bfloat162float(h0));
        __nv_bfloat16 l1 = __float2bfloat16(f[2*j+1] - __bfloat162float(h1));
        hu[j] = (uint32_t)__bfloat16_as_ushort(h0) | ((uint32_t)__bfloat16_as_ushort(h1) << 16);
        lu[j] = (uint32_t)__bfloat16_as_ushort(l0) | ((uint32_t)__bfloat16_as_ushort(l1) << 16);
    }
    ((uint2*)hi)[i] = make_uint2(hu[0], hu[1]);
    ((uint2*)lo)[i] = make_uint2(lu[0], lu[1]);
}

// ============================================================================
// HMMA split-bf16 GEMM:  C(128x128/CTA) = A @ B^T  via mma.sync m16n8k16
//   acc = Ah Bh^T + Ah Bl^T + Al Bh^T   (fp32 accum)
//   8 warps, warp tile 64x32 (4 mtiles x 4 ntiles), K-chunks of 32,
//   cp.async double-buffered smem, pitch 80B (conflict-free ldmatrix).
//   MODE 0: relu(acc+bias) -> split bf16 hi/lo
//   MODE 1: acc+bias -> fp32      MODE 2: acc -> fp32
// ============================================================================
#define TILE_BYTES  10240            // 128 rows x 80 B
#define STAGE_BYTES (4 * TILE_BYTES) // Ah, Al, Bh, Bl
#define GEMM_SMEM   (2 * STAGE_BYTES)

template<int MODE>
__global__ __launch_bounds__(256)
void gemm_tc(const __nv_bfloat16* __restrict__ Ah, const __nv_bfloat16* __restrict__ Al,
             const __nv_bfloat16* __restrict__ Bh, const __nv_bfloat16* __restrict__ Bl,
             const float* __restrict__ bias,
             float* __restrict__ outF,
             __nv_bfloat16* __restrict__ oHi, __nv_bfloat16* __restrict__ oLo) {
    extern __shared__ char smc[];
    const uint32_t sb = smem_u32(smc);
    const int tid = threadIdx.x;
    const int wid = tid >> 5, lane = tid & 31;
    const int wm = wid & 1, wn = wid >> 1;         // 2 x 4 warp grid
    const int row0 = blockIdx.y * 128;
    const int col0 = blockIdx.x * 128;

    const __nv_bfloat16* srcs[4] = {Ah, Al, Bh, Bl};

    // ---- cp.async one K-chunk (32 cols) of all 4 tiles into stage s ----
    auto cp_chunk = [&](int c, int s) {
        const int kb = c * 32;
        #pragma unroll
        for (int t = 0; t < 4; t++) {
            const char* src = (const char*)(srcs[t] + (size_t)((t < 2) ? row0 : col0) * CDIM + kb);
            uint32_t dst = sb + s * STAGE_BYTES + t * TILE_BYTES;
            #pragma unroll
            for (int i = 0; i < 2; i++) {
                int id = tid + i * 256;            // 0..511
                int r = id >> 2, q = id & 3;
                CP16(dst + r * 80 + q * 16, src + (size_t)r * (CDIM * 2) + q * 16);
            }
        }
    };

    float acc[4][4][4] = {};

    cp_chunk(0, 0); CP_COMMIT();

    for (int c = 0; c < 32; c++) {
        const int s = c & 1;
        if (c < 31) { cp_chunk(c + 1, s ^ 1); CP_COMMIT(); CP_WAIT(1); }
        else        { CP_WAIT(0); }
        __syncthreads();

        const uint32_t stg = sb + s * STAGE_BYTES;
        #pragma unroll
        for (int ks = 0; ks < 2; ks++) {
            uint32_t ah[4][4], al[4][4], bh[4][2], bl[4][2];
            {
                const int kk = ks * 16 + (lane >> 4) * 8;
                #pragma unroll
                for (int mt = 0; mt < 4; mt++) {
                    const int ra = wm * 64 + mt * 16 + (lane & 15);
                    uint32_t ad = stg + ra * 80 + kk * 2;
                    LDSM4(ah[mt], ad);
                    LDSM4(al[mt], ad + TILE_BYTES);
                }
            }
            {
                const int kk = ks * 16 + ((lane >> 3) & 1) * 8;
                #pragma unroll
                for (int nt = 0; nt < 4; nt++) {
                    const int rb = wn * 32 + nt * 8 + (lane & 7);
                    uint32_t bd = stg + 2 * TILE_BYTES + rb * 80 + kk * 2;
                    LDSM2(bh[nt], bd);
                    LDSM2(bl[nt], bd + TILE_BYTES);
                }
            }
            #pragma unroll
            for (int mt = 0; mt < 4; mt++)
                #pragma unroll
                for (int nt = 0; nt < 4; nt++) {
                    MMA_BF16(acc[mt][nt], ah[mt], bh[nt]);
                    MMA_BF16(acc[mt][nt], ah[mt], bl[nt]);
                    MMA_BF16(acc[mt][nt], al[mt], bh[nt]);
                }
        }
        __syncthreads();
    }

    // ---- epilogue straight from fragments ----
    const int g  = lane >> 2, th = lane & 3;
    #pragma unroll
    for (int mt = 0; mt < 4; mt++)
        #pragma unroll
        for (int nt = 0; nt < 4; nt++) {
            const int row = row0 + wm * 64 + mt * 16 + g;
            const int col = col0 + wn * 32 + nt * 8 + th * 2;
            float2 bv = make_float2(0.f, 0.f);
            if (MODE != 2) bv = *(const float2*)(bias + col);
            const float* cc = acc[mt][nt];
            #pragma unroll
            for (int h = 0; h < 2; h++) {          // h=0 -> row, h=1 -> row+8
                float v0 = cc[h * 2 + 0] + bv.x;
                float v1 = cc[h * 2 + 1] + bv.y;
                size_t o = (size_t)(row + h * 8) * CDIM + col;
                if (MODE == 0) {
                    v0 = fmaxf(v0, 0.f); v1 = fmaxf(v1, 0.f);
                    __nv_bfloat16 h0 = __float2bfloat16(v0);
                    __nv_bfloat16 h1 = __float2bfloat16(v1);
                    __nv_bfloat16 l0 = __float2bfloat16(v0 - __bfloat162float(h0));
                    __nv_bfloat16 l1 = __float2bfloat16(v1 - __bfloat162float(h1));
                    *(uint32_t*)(oHi + o) = (uint32_t)__bfloat16_as_ushort(h0) |
                                            ((uint32_t)__bfloat16_as_ushort(h1) << 16);
                    *(uint32_t*)(oLo + o) = (uint32_t)__bfloat16_as_ushort(l0) |
                                            ((uint32_t)__bfloat16_as_ushort(l1) << 16);
                } else {
                    *(float2*)(outF + o) = make_float2(v0, v1);
                }
            }
        }
}

// ============================================================================
// log(IoU + 1e-6) table
// ============================================================================
__global__ __launch_bounds__(256)
void logiou_kernel(const float* __restrict__ rois, float* __restrict__ li) {
    int idx = blockIdx.x * blockDim.x + threadIdx.x;
    int n = idx >> 11;
    int m = idx & 2047;
    const float* a = rois + n * 5 + 1;
    const float* b = rois + m * 5 + 1;
    float ax1 = a[0], ay1 = a[1], ax2 = a[2], ay2 = a[3];
    float bx1 = b[0], by1 = b[1], bx2 = b[2], by2 = b[3];
    float areaA = (ax2 - ax1 + 1.f) * (ay2 - ay1 + 1.f);
    float areaB = (bx2 - bx1 + 1.f) * (by2 - by1 + 1.f);
    float w = fminf(ax2, bx2) - fmaxf(ax1, bx1) + 1.f; w = fmaxf(w, 0.f);
    float h = fminf(ay2, by2) - fmaxf(ay1, by1) + 1.f; h = fmaxf(h, 0.f);
    float inter = w * h;
    float iou = inter / (areaA + areaB - inter);
    li[idx] = logf(iou + 1e-6f);
}

// ============================================================================
// fused flash attention, fp32 with packed f32x2 FMA in the hot loops
// ============================================================================
__global__ __launch_bounds__(256)
void flash_kernel(const float* __restrict__ X, const float* __restrict__ P,
                  const float* __restrict__ LI, const float* __restrict__ bout,
                  float* __restrict__ out) {
    constexpr int LDS = 68;
    extern __shared__ float sm[];
    float* Qs = sm;
    float* Ks = Qs + 64 * LDS;
    float* Vs = Ks + 64 * LDS;
    float* Ps = Vs + 64 * LDS;

    const int g  = blockIdx.y;
    const int n0 = blockIdx.x * 64;
    const int tid = threadIdx.x;
    const int tx = tid & 15;
    const int ty = tid >> 4;
    const int r0 = ty * 4;
    const int c0 = tx * 4;

    for (int i = tid; i < 64 * 16; i += 256) {
        int r  = i >> 4;
        int d0 = (i & 15) << 2;
        float4 v = *(const float4*)(X + (size_t)(n0 + r) * CDIM + g * DH + d0);
        Qs[(d0 + 0) * LDS + r] = v.x * 0.125f;
        Qs[(d0 + 1) * LDS + r] = v.y * 0.125f;
        Qs[(d0 + 2) * LDS + r] = v.z * 0.125f;
        Qs[(d0 + 3) * LDS + r] = v.w * 0.125f;
    }

    float m_i[4], l_i[4];
    uint64_t O2[4][2] = {};
    #pragma unroll
    for (int r = 0; r < 4; r++) { m_i[r] = -CUDART_INF_F; l_i[r] = 0.f; }

    for (int m0 = 0; m0 < NROI; m0 += 64) {
        __syncthreads();
        for (int i = tid; i < 64 * 16; i += 256) {
            int r  = i >> 4;
            int d0 = (i & 15) << 2;
            float4 kv = *(const float4*)(X + (size_t)(m0 + r) * CDIM + g * DH + d0);
            Ks[(d0 + 0) * LDS + r] = kv.x;
            Ks[(d0 + 1) * LDS + r] = kv.y;
            Ks[(d0 + 2) * LDS + r] = kv.z;
            Ks[(d0 + 3) * LDS + r] = kv.w;
            float4 vv = *(const float4*)(P + (size_t)(m0 + r) * CDIM + g * DH + d0);
            *(float4*)&Vs[r * LDS + d0] = vv;
        }
        __syncthreads();

        // ---- S = Q K^T via packed f32x2 ----
        uint64_t S2[4][2] = {};
        #pragma unroll 8
        for (int d = 0; d < 64; d++) {
            float4 q = *(const float4*)&Qs[d * LDS + r0];
            float4 k = *(const float4*)&Ks[d * LDS + c0];
            uint64_t k01 = pk2(k.x, k.y), k23 = pk2(k.z, k.w);
            uint64_t qd;
            qd = pk2(q.x, q.x); ffma2(S2[0][0], qd, k01); ffma2(S2[0][1], qd, k23);
            qd = pk2(q.y, q.y); ffma2(S2[1][0], qd, k01); ffma2(S2[1][1], qd, k23);
            qd = pk2(q.z, q.z); ffma2(S2[2][0], qd, k01); ffma2(S2[2][1], qd, k23);
            qd = pk2(q.w, q.w); ffma2(S2[3][0], qd, k01); ffma2(S2[3][1], qd, k23);
        }
        float S[4][4];
        #pragma unroll
        for (int r = 0; r < 4; r++) {
            upk2(S[r][0], S[r][1], S2[r][0]);
            upk2(S[r][2], S[r][3], S2[r][1]);
        }
        #pragma unroll
        for (int r = 0; r < 4; r++) {
            float4 b = *(const float4*)(LI + (size_t)(n0 + r0 + r) * NROI + m0 + c0);
            S[r][0] += b.x; S[r][1] += b.y; S[r][2] += b.z; S[r][3] += b.w;
        }

        // ---- online softmax ----
        #pragma unroll
        for (int r = 0; r < 4; r++) {
            float mt = fmaxf(fmaxf(S[r][0], S[r][1]), fmaxf(S[r][2], S[r][3]));
            #pragma unroll
            for (int off = 8; off; off >>= 1)
                mt = fmaxf(mt, __shfl_xor_sync(0xffffffffu, mt, off));
            float mn = fmaxf(m_i[r], mt);
            float alpha = __expf(m_i[r] - mn);
            m_i[r] = mn;
            float rs = 0.f;
            #pragma unroll
            for (int c = 0; c < 4; c++) {
                float p = __expf(S[r][c] - mn);
                Ps[(r0 + r) * LDS + c0 + c] = p;
                rs += p;
            }
            #pragma unroll
            for (int off = 8; off; off >>= 1)
                rs += __shfl_xor_sync(0xffffffffu, rs, off);
            l_i[r] = l_i[r] * alpha + rs;
            uint64_t ad = pk2(alpha, alpha);
            O2[r][0] = mul2(O2[r][0], ad);
            O2[r][1] = mul2(O2[r][1], ad);
        }
        __syncthreads();

        // ---- O += P_tile @ V_tile via packed f32x2 ----
        for (int m4 = 0; m4 < 64; m4 += 4) {
            float pr[4][4];
            #pragma unroll
            for (int r = 0; r < 4; r++) {
                float4 p4 = *(const float4*)&Ps[(r0 + r) * LDS + m4];
                pr[r][0] = p4.x; pr[r][1] = p4.y; pr[r][2] = p4.z; pr[r][3] = p4.w;
            }
            #pragma unroll
            for (int mm = 0; mm < 4; mm++) {
                float4 v = *(const float4*)&Vs[(m4 + mm) * LDS + c0];
                uint64_t v01 = pk2(v.x, v.y), v23 = pk2(v.z, v.w);
                #pragma unroll
                for (int r = 0; r < 4; r++) {
                    uint64_t pd = pk2(pr[r][mm], pr[r][mm]);
                    ffma2(O2[r][0], pd, v01);
                    ffma2(O2[r][1], pd, v23);
                }
            }
        }
    }

    float4 bo = *(const float4*)(bout + g * DH + c0);
    #pragma unroll
    for (int r = 0; r < 4; r++) {
        float O[4];
        upk2(O[0], O[1], O2[r][0]);
        upk2(O[2], O[3], O2[r][1]);
        float inv = 1.f / l_i[r];
        float4 o = make_float4(O[0] * inv + bo.x, O[1] * inv + bo.y,
                               O[2] * inv + bo.z, O[3] * inv + bo.w);
        *(float4*)(out + (size_t)(n0 + r0 + r) * CDIM + g * DH + c0) = o;
    }
}

// ============================================================================
// launch
// ============================================================================
extern "C" void kernel_launch(void* const* d_in, const int* in_sizes, int n_in,
                              void* d_out, int out_size) {
    const float* in_x = (const float*)d_in[0];
    const float* rois = (const float*)d_in[1];
    const float* W0   = (const float*)d_in[2];
    const float* b0   = (const float*)d_in[3];
    const float* W1   = (const float*)d_in[4];
    const float* b1   = (const float*)d_in[5];
    const float* Wout = (const float*)d_in[6];
    const float* bout = (const float*)d_in[7];
    float* out = (float*)d_out;

    void *pA0h,*pA0l,*pA1h,*pA1l,*pA2h,*pA2l,*pW0h,*pW0l,*pW1h,*pW1l,*pWph,*pWpl,*pX,*pP,*pLI;
    cudaGetSymbolAddress(&pA0h, g_A0h); cudaGetSymbolAddress(&pA0l, g_A0l);
    cudaGetSymbolAddress(&pA1h, g_A1h); cudaGetSymbolAddress(&pA1l, g_A1l);
    cudaGetSymbolAddress(&pA2h, g_A2h); cudaGetSymbolAddress(&pA2l, g_A2l);
    cudaGetSymbolAddress(&pW0h, g_W0h); cudaGetSymbolAddress(&pW0l, g_W0l);
    cudaGetSymbolAddress(&pW1h, g_W1h); cudaGetSymbolAddress(&pW1l, g_W1l);
    cudaGetSymbolAddress(&pWph, g_Wph); cudaGetSymbolAddress(&pWpl, g_Wpl);
    cudaGetSymbolAddress(&pX, g_X); cudaGetSymbolAddress(&pP, g_P);
    cudaGetSymbolAddress(&pLI, g_LI);

    const int nAct4 = NROI * CDIM / 4;
    const int nW4   = CDIM * CDIM / 4;

    // split inputs/weights into hi/lo bf16
    split_kernel<<<(nAct4 + 255)/256, 256>>>(in_x, (__nv_bfloat16*)pA0h, (__nv_bfloat16*)pA0l, nAct4, 1);
    split_kernel<<<(nAct4 + 255)/256, 256>>>(in_x, (__nv_bfloat16*)pA2h, (__nv_bfloat16*)pA2l, nAct4, 0);
    split_kernel<<<(nW4 + 255)/256, 256>>>(W0,   (__nv_bfloat16*)pW0h, (__nv_bfloat16*)pW0l, nW4, 0);
    split_kernel<<<(nW4 + 255)/256, 256>>>(W1,   (__nv_bfloat16*)pW1h, (__nv_bfloat16*)pW1l, nW4, 0);
    split_kernel<<<(nW4 + 255)/256, 256>>>(Wout, (__nv_bfloat16*)pWph, (__nv_bfloat16*)pWpl, nW4, 0);

    logiou_kernel<<<(NROI * NROI) / 256, 256>>>(rois, (float*)pLI);

    // HMMA GEMMs
    cudaFuncSetAttribute(gemm_tc<0>, cudaFuncAttributeMaxDynamicSharedMemorySize, GEMM_SMEM);
    cudaFuncSetAttribute(gemm_tc<1>, cudaFuncAttributeMaxDynamicSharedMemorySize, GEMM_SMEM);
    cudaFuncSetAttribute(gemm_tc<2>, cudaFuncAttributeMaxDynamicSharedMemorySize, GEMM_SMEM);
    dim3 ggrid(CDIM / 128, NROI / 128);    // 8 x 16 = 128 CTAs

    // GEMM0: relu(in_x)@W0^T + b0 -> relu -> split (A1)
    gemm_tc<0><<<ggrid, 256, GEMM_SMEM>>>((__nv_bfloat16*)pA0h, (__nv_bfloat16*)pA0l,
                                          (__nv_bfloat16*)pW0h, (__nv_bfloat16*)pW0l,
                                          b0, nullptr, (__nv_bfloat16*)pA1h, (__nv_bfloat16*)pA1l);
    // GEMM1: relu(H0)@W1^T + b1 -> X (fp32)
    gemm_tc<1><<<ggrid, 256, GEMM_SMEM>>>((__nv_bfloat16*)pA1h, (__nv_bfloat16*)pA1l,
                                          (__nv_bfloat16*)pW1h, (__nv_bfloat16*)pW1l,
                                          b1, (float*)pX, nullptr, nullptr);
    // GEMM2: in_x@Wout^T -> P (fp32)
    gemm_tc<2><<<ggrid, 256, GEMM_SMEM>>>((__nv_bfloat16*)pA2h, (__nv_bfloat16*)pA2l,
                                          (__nv_bfloat16*)pWph, (__nv_bfloat16*)pWpl,
                                          nullptr, (float*)pP, nullptr, nullptr);

    // fused attention
    size_t fsmem = 4 * 64 * 68 * sizeof(float);
    cudaFuncSetAttribute(flash_kernel, cudaFuncAttributeMaxDynamicSharedMemorySize, (int)fsmem);
    flash_kernel<<<dim3(NROI / 64, GRP), 256, fsmem>>>((float*)pX, (float*)pP,
                                                       (float*)pLI, bout, out);
}

// round 9
// speedup vs baseline: 2.6350x; 1.9436x over previous
#include <cuda_runtime.h>
#include <cuda_bf16.h>
#include <math_constants.h>
#include <cstdint>

#define NROI 2048
#define CDIM 1024
#define GRP  16
#define DH   64

// ============================================================================
// device scratch
// ============================================================================
__device__ __nv_bfloat16 g_A0h[NROI * CDIM], g_A0l[NROI * CDIM];   // split relu(in_x)
__device__ __nv_bfloat16 g_A1h[NROI * CDIM], g_A1l[NROI * CDIM];   // split relu(H0)
__device__ __nv_bfloat16 g_A2h[NROI * CDIM], g_A2l[NROI * CDIM];   // split in_x
__device__ __nv_bfloat16 g_W0h[CDIM * CDIM], g_W0l[CDIM * CDIM];
__device__ __nv_bfloat16 g_W1h[CDIM * CDIM], g_W1l[CDIM * CDIM];
__device__ __nv_bfloat16 g_Wph[CDIM * CDIM], g_Wpl[CDIM * CDIM];
__device__ __nv_bfloat16 g_Xh[NROI * CDIM], g_Xl[NROI * CDIM];     // embedded X (Q/K)
__device__ __nv_bfloat16 g_Vh[NROI * CDIM], g_Vl[NROI * CDIM];     // P = in_x@Wout^T (V)
__device__ float g_LI[NROI * NROI];                                 // log(iou + 1e-6)

// ============================================================================
// base-ISA PTX helpers (harness PTX target is plain sm_103 — no tcgen05)
// ============================================================================
__device__ __forceinline__ uint32_t smem_u32(const void* p) {
    uint32_t a;
    asm("{ .reg .u64 t; cvta.to.shared.u64 t, %1; cvt.u32.u64 %0, t; }" : "=r"(a) : "l"(p));
    return a;
}
#define LDSM4(r, addr) \
    asm volatile("ldmatrix.sync.aligned.m8n8.x4.shared.b16 {%0,%1,%2,%3}, [%4];" \
        : "=r"((r)[0]), "=r"((r)[1]), "=r"((r)[2]), "=r"((r)[3]) : "r"(addr))
#define LDSM4T(r, addr) \
    asm volatile("ldmatrix.sync.aligned.m8n8.x4.trans.shared.b16 {%0,%1,%2,%3}, [%4];" \
        : "=r"((r)[0]), "=r"((r)[1]), "=r"((r)[2]), "=r"((r)[3]) : "r"(addr))
#define LDSM2(r, addr) \
    asm volatile("ldmatrix.sync.aligned.m8n8.x2.shared.b16 {%0,%1}, [%2];" \
        : "=r"((r)[0]), "=r"((r)[1]) : "r"(addr))
#define MMA_BF16(c, a, b) \
    asm volatile("mma.sync.aligned.m16n8k16.row.col.f32.bf16.bf16.f32 " \
        "{%0,%1,%2,%3}, {%4,%5,%6,%7}, {%8,%9}, {%0,%1,%2,%3};" \
        : "+f"((c)[0]), "+f"((c)[1]), "+f"((c)[2]), "+f"((c)[3]) \
        : "r"((a)[0]), "r"((a)[1]), "r"((a)[2]), "r"((a)[3]), "r"((b)[0]), "r"((b)[1]))
#define CP16(dst, src)  asm volatile("cp.async.cg.shared.global [%0], [%1], 16;" :: "r"(dst), "l"(src))
#define CP_COMMIT()     asm volatile("cp.async.commit_group;" ::: "memory")
#define CP_WAIT(n)      asm volatile("cp.async.wait_group %0;" :: "n"(n) : "memory")

__device__ __forceinline__ uint32_t bf2pk(float hi, float lo) {
    uint32_t r; asm("cvt.rn.bf16x2.f32 %0, %1, %2;" : "=r"(r) : "f"(hi), "f"(lo)); return r;
}

// ============================================================================
// split kernel: fp32 -> (hi, lo) bf16, optional relu
// ============================================================================
__global__ __launch_bounds__(256)
void split_kernel(const float* __restrict__ in, __nv_bfloat16* __restrict__ hi,
                  __nv_bfloat16* __restrict__ lo, int n4, int relu) {
    int i = blockIdx.x * blockDim.x + threadIdx.x;
    if (i >= n4) return;
    float4 v = ((const float4*)in)[i];
    if (relu) {
        v.x = fmaxf(v.x, 0.f); v.y = fmaxf(v.y, 0.f);
        v.z = fmaxf(v.z, 0.f); v.w = fmaxf(v.w, 0.f);
    }
    float f[4] = {v.x, v.y, v.z, v.w};
    uint32_t hu[2], lu[2];
    #pragma unroll
    for (int j = 0; j < 2; j++) {
        uint32_t h = bf2pk(f[2*j+1], f[2*j]);
        float e0 = __uint_as_float(h << 16);
        float e1 = __uint_as_float(h & 0xffff0000u);
        hu[j] = h;
        lu[j] = bf2pk(f[2*j+1] - e1, f[2*j] - e0);
    }
    ((uint2*)hi)[i] = make_uint2(hu[0], hu[1]);
    ((uint2*)lo)[i] = make_uint2(lu[0], lu[1]);
}

// ============================================================================
// HMMA split-bf16 GEMM: C(128x128/CTA) = A @ B^T, always emits split bf16 out
//   MODE 0: relu(acc+bias)   MODE 1: acc+bias   MODE 2: acc
// ============================================================================
#define TILE_BYTES  10240            // 128 rows x 80 B
#define STAGE_BYTES (4 * TILE_BYTES)
#define GEMM_SMEM   (2 * STAGE_BYTES)

template<int MODE>
__global__ __launch_bounds__(256)
void gemm_tc(const __nv_bfloat16* __restrict__ Ah, const __nv_bfloat16* __restrict__ Al,
             const __nv_bfloat16* __restrict__ Bh, const __nv_bfloat16* __restrict__ Bl,
             const float* __restrict__ bias,
             __nv_bfloat16* __restrict__ oHi, __nv_bfloat16* __restrict__ oLo) {
    extern __shared__ char smc[];
    const uint32_t sb = smem_u32(smc);
    const int tid = threadIdx.x;
    const int wid = tid >> 5, lane = tid & 31;
    const int wm = wid & 1, wn = wid >> 1;
    const int row0 = blockIdx.y * 128;
    const int col0 = blockIdx.x * 128;

    const __nv_bfloat16* srcs[4] = {Ah, Al, Bh, Bl};

    auto cp_chunk = [&](int c, int s) {
        const int kb = c * 32;
        #pragma unroll
        for (int t = 0; t < 4; t++) {
            const char* src = (const char*)(srcs[t] + (size_t)((t < 2) ? row0 : col0) * CDIM + kb);
            uint32_t dst = sb + s * STAGE_BYTES + t * TILE_BYTES;
            #pragma unroll
            for (int i = 0; i < 2; i++) {
                int id = tid + i * 256;
                int r = id >> 2, q = id & 3;
                CP16(dst + r * 80 + q * 16, src + (size_t)r * (CDIM * 2) + q * 16);
            }
        }
    };

    float acc[4][4][4] = {};
    cp_chunk(0, 0); CP_COMMIT();

    for (int c = 0; c < 32; c++) {
        const int s = c & 1;
        if (c < 31) { cp_chunk(c + 1, s ^ 1); CP_COMMIT(); CP_WAIT(1); }
        else        { CP_WAIT(0); }
        __syncthreads();

        const uint32_t stg = sb + s * STAGE_BYTES;
        #pragma unroll
        for (int ks = 0; ks < 2; ks++) {
            uint32_t ah[4][4], al[4][4], bh[4][2], bl[4][2];
            {
                const int kk = ks * 16 + (lane >> 4) * 8;
                #pragma unroll
                for (int mt = 0; mt < 4; mt++) {
                    const int ra = wm * 64 + mt * 16 + (lane & 15);
                    uint32_t ad = stg + ra * 80 + kk * 2;
                    LDSM4(ah[mt], ad);
                    LDSM4(al[mt], ad + TILE_BYTES);
                }
            }
            {
                const int kk = ks * 16 + ((lane >> 3) & 1) * 8;
                #pragma unroll
                for (int nt = 0; nt < 4; nt++) {
                    const int rb = wn * 32 + nt * 8 + (lane & 7);
                    uint32_t bd = stg + 2 * TILE_BYTES + rb * 80 + kk * 2;
                    LDSM2(bh[nt], bd);
                    LDSM2(bl[nt], bd + TILE_BYTES);
                }
            }
            #pragma unroll
            for (int mt = 0; mt < 4; mt++)
                #pragma unroll
                for (int nt = 0; nt < 4; nt++) {
                    MMA_BF16(acc[mt][nt], ah[mt], bh[nt]);
                    MMA_BF16(acc[mt][nt], ah[mt], bl[nt]);
                    MMA_BF16(acc[mt][nt], al[mt], bh[nt]);
                }
        }
        __syncthreads();
    }

    const int g = lane >> 2, th = lane & 3;
    #pragma unroll
    for (int mt = 0; mt < 4; mt++)
        #pragma unroll
        for (int nt = 0; nt < 4; nt++) {
            const int row = row0 + wm * 64 + mt * 16 + g;
            const int col = col0 + wn * 32 + nt * 8 + th * 2;
            float2 bv = make_float2(0.f, 0.f);
            if (MODE != 2) bv = *(const float2*)(bias + col);
            const float* cc = acc[mt][nt];
            #pragma unroll
            for (int h = 0; h < 2; h++) {
                float v0 = cc[h * 2 + 0] + bv.x;
                float v1 = cc[h * 2 + 1] + bv.y;
                if (MODE == 0) { v0 = fmaxf(v0, 0.f); v1 = fmaxf(v1, 0.f); }
                size_t o = (size_t)(row + h * 8) * CDIM + col;
                uint32_t hp = bf2pk(v1, v0);
                float e0 = __uint_as_float(hp << 16);
                float e1 = __uint_as_float(hp & 0xffff0000u);
                *(uint32_t*)(oHi + o) = hp;
                *(uint32_t*)(oLo + o) = bf2pk(v1 - e1, v0 - e0);
            }
        }
}

// ============================================================================
// log(IoU + 1e-6) table
// ============================================================================
__global__ __launch_bounds__(256)
void logiou_kernel(const float* __restrict__ rois, float* __restrict__ li) {
    int idx = blockIdx.x * blockDim.x + threadIdx.x;
    int n = idx >> 11;
    int m = idx & 2047;
    const float* a = rois + n * 5 + 1;
    const float* b = rois + m * 5 + 1;
    float ax1 = a[0], ay1 = a[1], ax2 = a[2], ay2 = a[3];
    float bx1 = b[0], by1 = b[1], bx2 = b[2], by2 = b[3];
    float areaA = (ax2 - ax1 + 1.f) * (ay2 - ay1 + 1.f);
    float areaB = (bx2 - bx1 + 1.f) * (by2 - by1 + 1.f);
    float w = fminf(ax2, bx2) - fmaxf(ax1, bx1) + 1.f; w = fmaxf(w, 0.f);
    float h = fminf(ay2, by2) - fmaxf(ay1, by1) + 1.f; h = fmaxf(h, 0.f);
    float inter = w * h;
    float iou = inter / (areaA + areaB - inter);
    li[idx] = logf(iou + 1e-6f);
}

// ============================================================================
// HMMA flash attention (FA2 mma.sync structure, split-bf16 operands)
//   CTA: 128 q-rows x 1 group, 8 warps (16 q-rows each), kv tiles of 64
//   S = Q K^T (3 split MMAs), score = S/8 + LI (direct LDG),
//   online softmax in fragments, P repacked reg->reg into A-frags (hi/lo),
//   O += P V (3 split MMAs, V via ldmatrix.trans)
// ============================================================================
#define FP 144                         // smem pitch bytes (128B row + 16)
#define QOFF(h)     ((h) * (128 * FP))
#define SOFF(s, t)  (2 * 128 * FP + (s) * (4 * 64 * FP) + (t) * (64 * FP))
#define FLASH_SMEM  (2 * 128 * FP + 2 * 4 * 64 * FP)   // 110592 B

__global__ __launch_bounds__(256)
void flash_hmma(const __nv_bfloat16* __restrict__ Xh, const __nv_bfloat16* __restrict__ Xl,
                const __nv_bfloat16* __restrict__ Vh, const __nv_bfloat16* __restrict__ Vl,
                const float* __restrict__ LI, const float* __restrict__ bout,
                float* __restrict__ out) {
    extern __shared__ char smc[];
    const uint32_t sb = smem_u32(smc);
    const int tid = threadIdx.x;
    const int wid = tid >> 5, lane = tid & 31;
    const int g = lane >> 2, th = lane & 3;
    const int n0 = blockIdx.x * 128;
    const int grp = blockIdx.y;
    const size_t gcol = (size_t)grp * DH;

    const __nv_bfloat16* kvsrc[4] = {Xh, Xl, Vh, Vl};

    // ---- cp.async: Q (hi/lo, 128x64) once ----
    {
        #pragma unroll
        for (int i = 0; i < 8; i++) {
            int id = tid + i * 256;                  // 0..2047
            int t = id >> 10, rem = id & 1023;
            int r = rem >> 3, q = rem & 7;
            const char* src = (const char*)((t ? Xl : Xh) + (size_t)(n0 + r) * CDIM + gcol) + q * 16;
            CP16(sb + QOFF(t) + r * FP + q * 16, src);
        }
    }
    // ---- cp.async one kv stage (K hi/lo + V hi/lo, 64 rows) ----
    auto cp_kv = [&](int it, int s) {
        const int m0 = it * 64;
        #pragma unroll
        for (int i = 0; i < 8; i++) {
            int id = tid + i * 256;                  // 0..2047
            int t = id >> 9, rem = id & 511;
            int r = rem >> 3, q = rem & 7;
            const char* src = (const char*)(kvsrc[t] + (size_t)(m0 + r) * CDIM + gcol) + q * 16;
            CP16(sb + SOFF(s, t), src);              // placeholder, fixed below
            (void)src;
        }
    };
    // (lambda above can't use two dst args cleanly; re-do inline)
    #undef CPKV
    auto cp_kv2 = [&](int it, int s) {
        const int m0 = it * 64;
        #pragma unroll
        for (int i = 0; i < 8; i++) {
            int id = tid + i * 256;
            int t = id >> 9, rem = id & 511;
            int r = rem >> 3, q = rem & 7;
            uint32_t dst = sb + SOFF(s, t) + r * FP + q * 16;
            const char* src = (const char*)(kvsrc[t] + (size_t)(m0 + r) * CDIM + gcol) + q * 16;
            CP16(dst, src);
        }
    };

    cp_kv2(0, 0);
    CP_COMMIT();
    CP_WAIT(0);
    __syncthreads();

    // ---- Q fragments (kept in registers for all 32 kv iterations) ----
    uint32_t qa[2][4][4];
    #pragma unroll
    for (int h = 0; h < 2; h++)
        #pragma unroll
        for (int kt = 0; kt < 4; kt++) {
            uint32_t ad = sb + QOFF(h) + (wid * 16 + (lane & 15)) * FP
                        + (kt * 16 + (lane >> 4) * 8) * 2;
            LDSM4(qa[h][kt], ad);
        }

    float accO[8][4] = {};
    float mi0 = -CUDART_INF_F, mi1 = -CUDART_INF_F;
    float ls0 = 0.f, ls1 = 0.f;

    const float* lbase = LI + (size_t)(n0 + wid * 16 + g) * NROI + 2 * th;

    for (int it = 0; it < 32; it++) {
        const int s = it & 1;

        // prefetch LI early (independent of smem)
        float2 liA[8], liB[8];
        {
            const float* lp = lbase + it * 64;
            #pragma unroll
            for (int nt = 0; nt < 8; nt++) {
                liA[nt] = *(const float2*)(lp + nt * 8);
                liB[nt] = *(const float2*)(lp + 8 * NROI + nt * 8);
            }
        }

        if (it < 31) { cp_kv2(it + 1, s ^ 1); CP_COMMIT(); CP_WAIT(1); }
        else         { CP_WAIT(0); }
        __syncthreads();

        const uint32_t stK = sb + SOFF(s, 0);
        const uint32_t stV = sb + SOFF(s, 2);

        // ---- S = Q K^T ----
        float accS[8][4] = {};
        #pragma unroll
        for (int kt = 0; kt < 4; kt++) {
            uint32_t kh[4][4], kl[4][4];
            #pragma unroll
            for (int p = 0; p < 4; p++) {
                uint32_t ad = stK + (p * 16 + (lane & 15)) * FP
                            + (kt * 16 + (lane >> 4) * 8) * 2;
                LDSM4(kh[p], ad);
                LDSM4(kl[p], ad + 64 * FP);
            }
            #pragma unroll
            for (int p = 0; p < 4; p++) {
                uint32_t b0h[2] = {kh[p][0], kh[p][2]}, b1h[2] = {kh[p][1], kh[p][3]};
                uint32_t b0l[2] = {kl[p][0], kl[p][2]}, b1l[2] = {kl[p][1], kl[p][3]};
                MMA_BF16(accS[2*p],   qa[0][kt], b0h);
                MMA_BF16(accS[2*p],   qa[0][kt], b0l);
                MMA_BF16(accS[2*p],   qa[1][kt], b0h);
                MMA_BF16(accS[2*p+1], qa[0][kt], b1h);
                MMA_BF16(accS[2*p+1], qa[0][kt], b1l);
                MMA_BF16(accS[2*p+1], qa[1][kt], b1h);
            }
        }

        // ---- scores = S/8 + LI ----
        #pragma unroll
        for (int nt = 0; nt < 8; nt++) {
            accS[nt][0] = fmaf(accS[nt][0], 0.125f, liA[nt].x);
            accS[nt][1] = fmaf(accS[nt][1], 0.125f, liA[nt].y);
            accS[nt][2] = fmaf(accS[nt][2], 0.125f, liB[nt].x);
            accS[nt][3] = fmaf(accS[nt][3], 0.125f, liB[nt].y);
        }

        // ---- online softmax (rows g / g+8, quad reduce over th lanes) ----
        float mt0 = -CUDART_INF_F, mt1 = -CUDART_INF_F;
        #pragma unroll
        for (int nt = 0; nt < 8; nt++) {
            mt0 = fmaxf(mt0, fmaxf(accS[nt][0], accS[nt][1]));
            mt1 = fmaxf(mt1, fmaxf(accS[nt][2], accS[nt][3]));
        }
        mt0 = fmaxf(mt0, __shfl_xor_sync(0xffffffffu, mt0, 1));
        mt0 = fmaxf(mt0, __shfl_xor_sync(0xffffffffu, mt0, 2));
        mt1 = fmaxf(mt1, __shfl_xor_sync(0xffffffffu, mt1, 1));
        mt1 = fmaxf(mt1, __shfl_xor_sync(0xffffffffu, mt1, 2));
        float mn0 = fmaxf(mi0, mt0), mn1 = fmaxf(mi1, mt1);
        float al0 = __expf(mi0 - mn0), al1 = __expf(mi1 - mn1);
        mi0 = mn0; mi1 = mn1;

        uint32_t pah[4][4], pal[4][4];
        float rs0 = 0.f, rs1 = 0.f;
        #pragma unroll
        for (int nt = 0; nt < 8; nt++) {
            float p0 = __expf(accS[nt][0] - mn0);
            float p1 = __expf(accS[nt][1] - mn0);
            float p2 = __expf(accS[nt][2] - mn1);
            float p3 = __expf(accS[nt][3] - mn1);
            rs0 += p0 + p1; rs1 += p2 + p3;
            uint32_t hA = bf2pk(p1, p0);
            uint32_t hB = bf2pk(p3, p2);
            float e0 = __uint_as_float(hA << 16), e1 = __uint_as_float(hA & 0xffff0000u);
            float e2 = __uint_as_float(hB << 16), e3 = __uint_as_float(hB & 0xffff0000u);
            uint32_t lA = bf2pk(p1 - e1, p0 - e0);
            uint32_t lB = bf2pk(p3 - e3, p2 - e2);
            int kt = nt >> 1, off = (nt & 1) * 2;
            pah[kt][off] = hA; pah[kt][off + 1] = hB;
            pal[kt][off] = lA; pal[kt][off + 1] = lB;
        }
        rs0 += __shfl_xor_sync(0xffffffffu, rs0, 1);
        rs0 += __shfl_xor_sync(0xffffffffu, rs0, 2);
        rs1 += __shfl_xor_sync(0xffffffffu, rs1, 1);
        rs1 += __shfl_xor_sync(0xffffffffu, rs1, 2);
        ls0 = ls0 * al0 + rs0;
        ls1 = ls1 * al1 + rs1;

        #pragma unroll
        for (int nt = 0; nt < 8; nt++) {
            accO[nt][0] *= al0; accO[nt][1] *= al0;
            accO[nt][2] *= al1; accO[nt][3] *= al1;
        }

        // ---- O += P V ----
        #pragma unroll
        for (int kt = 0; kt < 4; kt++) {
            uint32_t vh[4][4], vl[4][4];
            #pragma unroll
            for (int db = 0; db < 4; db++) {
                uint32_t ad = stV + (kt * 16 + (lane & 15)) * FP
                            + (db * 16 + (lane >> 4) * 8) * 2;
                LDSM4T(vh[db], ad);
                LDSM4T(vl[db], ad + 64 * FP);
            }
            #pragma unroll
            for (int db = 0; db < 4; db++) {
                uint32_t bh0[2] = {vh[db][0], vh[db][1]}, bh1[2] = {vh[db][2], vh[db][3]};
                uint32_t bl0[2] = {vl[db][0], vl[db][1]}, bl1[2] = {vl[db][2], vl[db][3]};
                MMA_BF16(accO[2*db],   pah[kt], bh0);
                MMA_BF16(accO[2*db],   pah[kt], bl0);
                MMA_BF16(accO[2*db],   pal[kt], bh0);
                MMA_BF16(accO[2*db+1], pah[kt], bh1);
                MMA_BF16(accO[2*db+1], pah[kt], bl1);
                MMA_BF16(accO[2*db+1], pal[kt], bh1);
            }
        }
        __syncthreads();   // stage s free for next prefetch
    }

    // ---- epilogue: O/l + bout ----
    const float inv0 = 1.f / ls0, inv1 = 1.f / ls1;
    #pragma unroll
    for (int nt = 0; nt < 8; nt++) {
        const int col = grp * DH + nt * 8 + 2 * th;
        float2 bo = *(const float2*)(bout + col);
        const int row = n0 + wid * 16 + g;
        *(float2*)(out + (size_t)row * CDIM + col) =
            make_float2(accO[nt][0] * inv0 + bo.x, accO[nt][1] * inv0 + bo.y);
        *(float2*)(out + (size_t)(row + 8) * CDIM + col) =
            make_float2(accO[nt][2] * inv1 + bo.x, accO[nt][3] * inv1 + bo.y);
    }
}

// ============================================================================
// launch
// ============================================================================
extern "C" void kernel_launch(void* const* d_in, const int* in_sizes, int n_in,
                              void* d_out, int out_size) {
    const float* in_x = (const float*)d_in[0];
    const float* rois = (const float*)d_in[1];
    const float* W0   = (const float*)d_in[2];
    const float* b0   = (const float*)d_in[3];
    const float* W1   = (const float*)d_in[4];
    const float* b1   = (const float*)d_in[5];
    const float* Wout = (const float*)d_in[6];
    const float* bout = (const float*)d_in[7];
    float* out = (float*)d_out;

    void *pA0h,*pA0l,*pA1h,*pA1l,*pA2h,*pA2l,*pW0h,*pW0l,*pW1h,*pW1l,*pWph,*pWpl;
    void *pXh,*pXl,*pVh,*pVl,*pLI;
    cudaGetSymbolAddress(&pA0h, g_A0h); cudaGetSymbolAddress(&pA0l, g_A0l);
    cudaGetSymbolAddress(&pA1h, g_A1h); cudaGetSymbolAddress(&pA1l, g_A1l);
    cudaGetSymbolAddress(&pA2h, g_A2h); cudaGetSymbolAddress(&pA2l, g_A2l);
    cudaGetSymbolAddress(&pW0h, g_W0h); cudaGetSymbolAddress(&pW0l, g_W0l);
    cudaGetSymbolAddress(&pW1h, g_W1h); cudaGetSymbolAddress(&pW1l, g_W1l);
    cudaGetSymbolAddress(&pWph, g_Wph); cudaGetSymbolAddress(&pWpl, g_Wpl);
    cudaGetSymbolAddress(&pXh, g_Xh);   cudaGetSymbolAddress(&pXl, g_Xl);
    cudaGetSymbolAddress(&pVh, g_Vh);   cudaGetSymbolAddress(&pVl, g_Vl);
    cudaGetSymbolAddress(&pLI, g_LI);

    const int nAct4 = NROI * CDIM / 4;
    const int nW4   = CDIM * CDIM / 4;

    split_kernel<<<(nAct4 + 255)/256, 256>>>(in_x, (__nv_bfloat16*)pA0h, (__nv_bfloat16*)pA0l, nAct4, 1);
    split_kernel<<<(nAct4 + 255)/256, 256>>>(in_x, (__nv_bfloat16*)pA2h, (__nv_bfloat16*)pA2l, nAct4, 0);
    split_kernel<<<(nW4 + 255)/256, 256>>>(W0,   (__nv_bfloat16*)pW0h, (__nv_bfloat16*)pW0l, nW4, 0);
    split_kernel<<<(nW4 + 255)/256, 256>>>(W1,   (__nv_bfloat16*)pW1h, (__nv_bfloat16*)pW1l, nW4, 0);
    split_kernel<<<(nW4 + 255)/256, 256>>>(Wout, (__nv_bfloat16*)pWph, (__nv_bfloat16*)pWpl, nW4, 0);

    logiou_kernel<<<(NROI * NROI) / 256, 256>>>(rois, (float*)pLI);

    cudaFuncSetAttribute(gemm_tc<0>, cudaFuncAttributeMaxDynamicSharedMemorySize, GEMM_SMEM);
    cudaFuncSetAttribute(gemm_tc<1>, cudaFuncAttributeMaxDynamicSharedMemorySize, GEMM_SMEM);
    cudaFuncSetAttribute(gemm_tc<2>, cudaFuncAttributeMaxDynamicSharedMemorySize, GEMM_SMEM);
    dim3 ggrid(CDIM / 128, NROI / 128);

    // GEMM0: relu(relu(in_x)@W0^T + b0) -> A1 split
    gemm_tc<0><<<ggrid, 256, GEMM_SMEM>>>((__nv_bfloat16*)pA0h, (__nv_bfloat16*)pA0l,
                                          (__nv_bfloat16*)pW0h, (__nv_bfloat16*)pW0l,
                                          b0, (__nv_bfloat16*)pA1h, (__nv_bfloat16*)pA1l);
    // GEMM1: relu(H0)@W1^T + b1 -> X split (flash Q/K)
    gemm_tc<1><<<ggrid, 256, GEMM_SMEM>>>((__nv_bfloat16*)pA1h, (__nv_bfloat16*)pA1l,
                                          (__nv_bfloat16*)pW1h, (__nv_bfloat16*)pW1l,
                                          b1, (__nv_bfloat16*)pXh, (__nv_bfloat16*)pXl);
    // GEMM2: in_x@Wout^T -> V split (flash V)
    gemm_tc<2><<<ggrid, 256, GEMM_SMEM>>>((__nv_bfloat16*)pA2h, (__nv_bfloat16*)pA2l,
                                          (__nv_bfloat16*)pWph, (__nv_bfloat16*)pWpl,
                                          nullptr, (__nv_bfloat16*)pVh, (__nv_bfloat16*)pVl);

    // HMMA flash attention
    cudaFuncSetAttribute(flash_hmma, cudaFuncAttributeMaxDynamicSharedMemorySize, FLASH_SMEM);
    flash_hmma<<<dim3(NROI / 128, GRP), 256, FLASH_SMEM>>>(
        (__nv_bfloat16*)pXh, (__nv_bfloat16*)pXl,
        (__nv_bfloat16*)pVh, (__nv_bfloat16*)pVl,
        (float*)pLI, bout, out);
}

// round 10
// speedup vs baseline: 2.8549x; 1.0835x over previous
#include <cuda_runtime.h>
#include <cuda_bf16.h>
#include <cuda_fp16.h>
#include <math_constants.h>
#include <cstdint>

#define NROI 2048
#define CDIM 1024
#define GRP  16
#define DH   64

// ============================================================================
// device scratch
// ============================================================================
__device__ __nv_bfloat16 g_A0h[NROI * CDIM], g_A0l[NROI * CDIM];   // split relu(in_x)
__device__ __nv_bfloat16 g_A1h[NROI * CDIM], g_A1l[NROI * CDIM];   // split relu(H0)
__device__ __nv_bfloat16 g_A2h[NROI * CDIM], g_A2l[NROI * CDIM];   // split in_x
__device__ __nv_bfloat16 g_W0h[CDIM * CDIM], g_W0l[CDIM * CDIM];
__device__ __nv_bfloat16 g_W1h[CDIM * CDIM], g_W1l[CDIM * CDIM];
__device__ __nv_bfloat16 g_Wph[CDIM * CDIM], g_Wpl[CDIM * CDIM];
__device__ __nv_bfloat16 g_Xh[NROI * CDIM], g_Xl[NROI * CDIM];     // embedded X (Q/K), bf16 split
__device__ __half        g_Vh[NROI * CDIM], g_Vl[NROI * CDIM];     // V = in_x@Wout^T, fp16 split
__device__ float g_LI[NROI * NROI];                                 // log2(iou + 1e-6)

// ============================================================================
// base-ISA PTX helpers (harness PTX target is plain sm_103 — no tcgen05)
// ============================================================================
__device__ __forceinline__ uint32_t smem_u32(const void* p) {
    uint32_t a;
    asm("{ .reg .u64 t; cvta.to.shared.u64 t, %1; cvt.u32.u64 %0, t; }" : "=r"(a) : "l"(p));
    return a;
}
#define LDSM4(r, addr) \
    asm volatile("ldmatrix.sync.aligned.m8n8.x4.shared.b16 {%0,%1,%2,%3}, [%4];" \
        : "=r"((r)[0]), "=r"((r)[1]), "=r"((r)[2]), "=r"((r)[3]) : "r"(addr))
#define LDSM4T(r, addr) \
    asm volatile("ldmatrix.sync.aligned.m8n8.x4.trans.shared.b16 {%0,%1,%2,%3}, [%4];" \
        : "=r"((r)[0]), "=r"((r)[1]), "=r"((r)[2]), "=r"((r)[3]) : "r"(addr))
#define LDSM2(r, addr) \
    asm volatile("ldmatrix.sync.aligned.m8n8.x2.shared.b16 {%0,%1}, [%2];" \
        : "=r"((r)[0]), "=r"((r)[1]) : "r"(addr))
#define MMA_BF16(c, a, b) \
    asm volatile("mma.sync.aligned.m16n8k16.row.col.f32.bf16.bf16.f32 " \
        "{%0,%1,%2,%3}, {%4,%5,%6,%7}, {%8,%9}, {%0,%1,%2,%3};" \
        : "+f"((c)[0]), "+f"((c)[1]), "+f"((c)[2]), "+f"((c)[3]) \
        : "r"((a)[0]), "r"((a)[1]), "r"((a)[2]), "r"((a)[3]), "r"((b)[0]), "r"((b)[1]))
#define MMA_F16(c, a, b) \
    asm volatile("mma.sync.aligned.m16n8k16.row.col.f32.f16.f16.f32 " \
        "{%0,%1,%2,%3}, {%4,%5,%6,%7}, {%8,%9}, {%0,%1,%2,%3};" \
        : "+f"((c)[0]), "+f"((c)[1]), "+f"((c)[2]), "+f"((c)[3]) \
        : "r"((a)[0]), "r"((a)[1]), "r"((a)[2]), "r"((a)[3]), "r"((b)[0]), "r"((b)[1]))
#define CP16(dst, src)  asm volatile("cp.async.cg.shared.global [%0], [%1], 16;" :: "r"(dst), "l"(src))
#define CP_COMMIT()     asm volatile("cp.async.commit_group;" ::: "memory")
#define CP_WAIT(n)      asm volatile("cp.async.wait_group %0;" :: "n"(n) : "memory")

__device__ __forceinline__ uint32_t bf2pk(float hi, float lo) {
    uint32_t r; asm("cvt.rn.bf16x2.f32 %0, %1, %2;" : "=r"(r) : "f"(hi), "f"(lo)); return r;
}
__device__ __forceinline__ uint32_t hf2pk(float hi, float lo) {
    uint32_t r; asm("cvt.rn.f16x2.f32 %0, %1, %2;" : "=r"(r) : "f"(hi), "f"(lo)); return r;
}
__device__ __forceinline__ float ex2f(float x) {
    float r; asm("ex2.approx.f32 %0, %1;" : "=f"(r) : "f"(x)); return r;
}

// ============================================================================
// merged split kernel: one launch for all 5 fp32 -> (hi, lo) bf16 splits
//   seg0 [0,2048):    relu(in_x) -> A0       seg1 [2048,4096): in_x -> A2
//   seg2 [4096,5120): W0          seg3 [5120,6144): W1   seg4 [6144,7168): Wout
// ============================================================================
__global__ __launch_bounds__(256)
void split_all(const float* __restrict__ in_x, const float* __restrict__ W0,
               const float* __restrict__ W1, const float* __restrict__ Wp,
               __nv_bfloat16* __restrict__ a0h, __nv_bfloat16* __restrict__ a0l,
               __nv_bfloat16* __restrict__ a2h, __nv_bfloat16* __restrict__ a2l,
               __nv_bfloat16* __restrict__ w0h, __nv_bfloat16* __restrict__ w0l,
               __nv_bfloat16* __restrict__ w1h, __nv_bfloat16* __restrict__ w1l,
               __nv_bfloat16* __restrict__ wph, __nv_bfloat16* __restrict__ wpl) {
    const int b = blockIdx.x;
    const float* src; __nv_bfloat16 *hi, *lo; int relu = 0, base;
    if      (b < 2048) { src = in_x; hi = a0h; lo = a0l; relu = 1; base = 0; }
    else if (b < 4096) { src = in_x; hi = a2h; lo = a2l; base = 2048; }
    else if (b < 5120) { src = W0;   hi = w0h; lo = w0l; base = 4096; }
    else if (b < 6144) { src = W1;   hi = w1h; lo = w1l; base = 5120; }
    else               { src = Wp;   hi = wph; lo = wpl; base = 6144; }
    int i = (b - base) * 256 + threadIdx.x;
    float4 v = ((const float4*)src)[i];
    if (relu) {
        v.x = fmaxf(v.x, 0.f); v.y = fmaxf(v.y, 0.f);
        v.z = fmaxf(v.z, 0.f); v.w = fmaxf(v.w, 0.f);
    }
    float f[4] = {v.x, v.y, v.z, v.w};
    uint32_t hu[2], lu[2];
    #pragma unroll
    for (int j = 0; j < 2; j++) {
        uint32_t h = bf2pk(f[2*j+1], f[2*j]);
        float e0 = __uint_as_float(h << 16);
        float e1 = __uint_as_float(h & 0xffff0000u);
        hu[j] = h;
        lu[j] = bf2pk(f[2*j+1] - e1, f[2*j] - e0);
    }
    ((uint2*)hi)[i] = make_uint2(hu[0], hu[1]);
    ((uint2*)lo)[i] = make_uint2(lu[0], lu[1]);
}

// ============================================================================
// HMMA split-bf16 GEMM: C(128x128/CTA) = A @ B^T
//   MODE 0: relu(acc+bias) -> bf16 hi/lo     MODE 1: acc+bias -> bf16 hi/lo
//   MODE 2: acc -> fp16 hi/lo (flash V)
// ============================================================================
#define TILE_BYTES  10240            // 128 rows x 80 B
#define STAGE_BYTES (4 * TILE_BYTES)
#define GEMM_SMEM   (2 * STAGE_BYTES)

template<int MODE>
__global__ __launch_bounds__(256)
void gemm_tc(const __nv_bfloat16* __restrict__ Ah, const __nv_bfloat16* __restrict__ Al,
             const __nv_bfloat16* __restrict__ Bh, const __nv_bfloat16* __restrict__ Bl,
             const float* __restrict__ bias,
             __nv_bfloat16* __restrict__ oHi, __nv_bfloat16* __restrict__ oLo) {
    extern __shared__ char smc[];
    const uint32_t sb = smem_u32(smc);
    const int tid = threadIdx.x;
    const int wid = tid >> 5, lane = tid & 31;
    const int wm = wid & 1, wn = wid >> 1;
    const int row0 = blockIdx.y * 128;
    const int col0 = blockIdx.x * 128;

    const __nv_bfloat16* srcs[4] = {Ah, Al, Bh, Bl};

    auto cp_chunk = [&](int c, int s) {
        const int kb = c * 32;
        #pragma unroll
        for (int t = 0; t < 4; t++) {
            const char* src = (const char*)(srcs[t] + (size_t)((t < 2) ? row0 : col0) * CDIM + kb);
            uint32_t dst = sb + s * STAGE_BYTES + t * TILE_BYTES;
            #pragma unroll
            for (int i = 0; i < 2; i++) {
                int id = tid + i * 256;
                int r = id >> 2, q = id & 3;
                CP16(dst + r * 80 + q * 16, src + (size_t)r * (CDIM * 2) + q * 16);
            }
        }
    };

    float acc[4][4][4] = {};
    cp_chunk(0, 0); CP_COMMIT();

    for (int c = 0; c < 32; c++) {
        const int s = c & 1;
        if (c < 31) { cp_chunk(c + 1, s ^ 1); CP_COMMIT(); CP_WAIT(1); }
        else        { CP_WAIT(0); }
        __syncthreads();

        const uint32_t stg = sb + s * STAGE_BYTES;
        #pragma unroll
        for (int ks = 0; ks < 2; ks++) {
            uint32_t ah[4][4], al[4][4], bh[4][2], bl[4][2];
            {
                const int kk = ks * 16 + (lane >> 4) * 8;
                #pragma unroll
                for (int mt = 0; mt < 4; mt++) {
                    const int ra = wm * 64 + mt * 16 + (lane & 15);
                    uint32_t ad = stg + ra * 80 + kk * 2;
                    LDSM4(ah[mt], ad);
                    LDSM4(al[mt], ad + TILE_BYTES);
                }
            }
            {
                const int kk = ks * 16 + ((lane >> 3) & 1) * 8;
                #pragma unroll
                for (int nt = 0; nt < 4; nt++) {
                    const int rb = wn * 32 + nt * 8 + (lane & 7);
                    uint32_t bd = stg + 2 * TILE_BYTES + rb * 80 + kk * 2;
                    LDSM2(bh[nt], bd);
                    LDSM2(bl[nt], bd + TILE_BYTES);
                }
            }
            #pragma unroll
            for (int mt = 0; mt < 4; mt++)
                #pragma unroll
                for (int nt = 0; nt < 4; nt++) {
                    MMA_BF16(acc[mt][nt], ah[mt], bh[nt]);
                    MMA_BF16(acc[mt][nt], ah[mt], bl[nt]);
                    MMA_BF16(acc[mt][nt], al[mt], bh[nt]);
                }
        }
        __syncthreads();
    }

    const int g = lane >> 2, th = lane & 3;
    #pragma unroll
    for (int mt = 0; mt < 4; mt++)
        #pragma unroll
        for (int nt = 0; nt < 4; nt++) {
            const int row = row0 + wm * 64 + mt * 16 + g;
            const int col = col0 + wn * 32 + nt * 8 + th * 2;
            float2 bv = make_float2(0.f, 0.f);
            if (MODE != 2) bv = *(const float2*)(bias + col);
            const float* cc = acc[mt][nt];
            #pragma unroll
            for (int h = 0; h < 2; h++) {
                float v0 = cc[h * 2 + 0] + bv.x;
                float v1 = cc[h * 2 + 1] + bv.y;
                if (MODE == 0) { v0 = fmaxf(v0, 0.f); v1 = fmaxf(v1, 0.f); }
                size_t o = (size_t)(row + h * 8) * CDIM + col;
                if (MODE == 2) {
                    uint32_t hp = hf2pk(v1, v0);
                    __half2 hh = *(__half2*)&hp;
                    float2 e = __half22float2(hh);     // e.x = lo half (v0), e.y = hi half (v1)
                    *(uint32_t*)(oHi + o) = hp;
                    *(uint32_t*)(oLo + o) = hf2pk(v1 - e.y, v0 - e.x);
                } else {
                    uint32_t hp = bf2pk(v1, v0);
                    float e0 = __uint_as_float(hp << 16);
                    float e1 = __uint_as_float(hp & 0xffff0000u);
                    *(uint32_t*)(oHi + o) = hp;
                    *(uint32_t*)(oLo + o) = bf2pk(v1 - e1, v0 - e0);
                }
            }
        }
}

// ============================================================================
// log2(IoU + 1e-6) table (log2 domain: exp via single ex2.approx downstream)
// ============================================================================
__global__ __launch_bounds__(256)
void logiou_kernel(const float* __restrict__ rois, float* __restrict__ li) {
    int idx = blockIdx.x * blockDim.x + threadIdx.x;
    int n = idx >> 11;
    int m = idx & 2047;
    const float* a = rois + n * 5 + 1;
    const float* b = rois + m * 5 + 1;
    float ax1 = a[0], ay1 = a[1], ax2 = a[2], ay2 = a[3];
    float bx1 = b[0], by1 = b[1], bx2 = b[2], by2 = b[3];
    float areaA = (ax2 - ax1 + 1.f) * (ay2 - ay1 + 1.f);
    float areaB = (bx2 - bx1 + 1.f) * (by2 - by1 + 1.f);
    float w = fminf(ax2, bx2) - fmaxf(ax1, bx1) + 1.f; w = fmaxf(w, 0.f);
    float h = fminf(ay2, by2) - fmaxf(ay1, by1) + 1.f; h = fmaxf(h, 0.f);
    float inter = w * h;
    float iou = inter / (areaA + areaB - inter);
    li[idx] = __log2f(iou + 1e-6f);
}

// ============================================================================
// HMMA flash attention
//   S = Q K^T (bf16 3-MMA split), scores in log2 domain,
//   P single fp16 (scaled by 2^10; normalization cancels), V fp16 hi/lo,
//   O += P V (2-MMA split) — 160 MMAs/warp/iter vs 192 before.
// ============================================================================
#define FP 144
#define QOFF(h)     ((h) * (128 * FP))
#define SOFF(s, t)  (2 * 128 * FP + (s) * (4 * 64 * FP) + (t) * (64 * FP))
#define FLASH_SMEM  (2 * 128 * FP + 2 * 4 * 64 * FP)   // 110592 B
#define SCL8_LOG2E  0.1803368801111204f                 // 0.125 * log2(e)

__global__ __launch_bounds__(256)
void flash_hmma(const __nv_bfloat16* __restrict__ Xh, const __nv_bfloat16* __restrict__ Xl,
                const __nv_bfloat16* __restrict__ Vh, const __nv_bfloat16* __restrict__ Vl,
                const float* __restrict__ LI, const float* __restrict__ bout,
                float* __restrict__ out) {
    extern __shared__ char smc[];
    const uint32_t sb = smem_u32(smc);
    const int tid = threadIdx.x;
    const int wid = tid >> 5, lane = tid & 31;
    const int g = lane >> 2, th = lane & 3;
    const int n0 = blockIdx.x * 128;
    const int grp = blockIdx.y;
    const size_t gcol = (size_t)grp * DH;

    const __nv_bfloat16* kvsrc[4] = {Xh, Xl, Vh, Vl};

    // ---- cp.async: Q (hi/lo, 128x64) once ----
    #pragma unroll
    for (int i = 0; i < 8; i++) {
        int id = tid + i * 256;
        int t = id >> 10, rem = id & 1023;
        int r = rem >> 3, q = rem & 7;
        const char* src = (const char*)((t ? Xl : Xh) + (size_t)(n0 + r) * CDIM + gcol) + q * 16;
        CP16(sb + QOFF(t) + r * FP + q * 16, src);
    }
    auto cp_kv = [&](int it, int s) {
        const int m0 = it * 64;
        #pragma unroll
        for (int i = 0; i < 8; i++) {
            int id = tid + i * 256;
            int t = id >> 9, rem = id & 511;
            int r = rem >> 3, q = rem & 7;
            uint32_t dst = sb + SOFF(s, t) + r * FP + q * 16;
            const char* src = (const char*)(kvsrc[t] + (size_t)(m0 + r) * CDIM + gcol) + q * 16;
            CP16(dst, src);
        }
    };

    cp_kv(0, 0);
    CP_COMMIT();
    CP_WAIT(0);
    __syncthreads();

    // ---- Q fragments resident for all iterations ----
    uint32_t qa[2][4][4];
    #pragma unroll
    for (int h = 0; h < 2; h++)
        #pragma unroll
        for (int kt = 0; kt < 4; kt++) {
            uint32_t ad = sb + QOFF(h) + (wid * 16 + (lane & 15)) * FP
                        + (kt * 16 + (lane >> 4) * 8) * 2;
            LDSM4(qa[h][kt], ad);
        }

    float accO[8][4] = {};
    float mi0 = -CUDART_INF_F, mi1 = -CUDART_INF_F;
    float ls0 = 0.f, ls1 = 0.f;

    const float* lbase = LI + (size_t)(n0 + wid * 16 + g) * NROI + 2 * th;

    for (int it = 0; it < 32; it++) {
        const int s = it & 1;

        float2 liA[8], liB[8];
        {
            const float* lp = lbase + it * 64;
            #pragma unroll
            for (int nt = 0; nt < 8; nt++) {
                liA[nt] = *(const float2*)(lp + nt * 8);
                liB[nt] = *(const float2*)(lp + 8 * NROI + nt * 8);
            }
        }

        if (it < 31) { cp_kv(it + 1, s ^ 1); CP_COMMIT(); CP_WAIT(1); }
        else         { CP_WAIT(0); }
        __syncthreads();

        const uint32_t stK = sb + SOFF(s, 0);
        const uint32_t stV = sb + SOFF(s, 2);

        // ---- S = Q K^T (bf16 split) ----
        float accS[8][4] = {};
        #pragma unroll
        for (int kt = 0; kt < 4; kt++) {
            uint32_t kh[4][4], kl[4][4];
            #pragma unroll
            for (int p = 0; p < 4; p++) {
                uint32_t ad = stK + (p * 16 + (lane & 15)) * FP
                            + (kt * 16 + (lane >> 4) * 8) * 2;
                LDSM4(kh[p], ad);
                LDSM4(kl[p], ad + 64 * FP);
            }
            #pragma unroll
            for (int p = 0; p < 4; p++) {
                uint32_t b0h[2] = {kh[p][0], kh[p][2]}, b1h[2] = {kh[p][1], kh[p][3]};
                uint32_t b0l[2] = {kl[p][0], kl[p][2]}, b1l[2] = {kl[p][1], kl[p][3]};
                MMA_BF16(accS[2*p],   qa[0][kt], b0h);
                MMA_BF16(accS[2*p],   qa[0][kt], b0l);
                MMA_BF16(accS[2*p],   qa[1][kt], b0h);
                MMA_BF16(accS[2*p+1], qa[0][kt], b1h);
                MMA_BF16(accS[2*p+1], qa[0][kt], b1l);
                MMA_BF16(accS[2*p+1], qa[1][kt], b1h);
            }
        }

        // ---- scores (log2 domain) = S * 0.125*log2e + LI2 ----
        #pragma unroll
        for (int nt = 0; nt < 8; nt++) {
            accS[nt][0] = fmaf(accS[nt][0], SCL8_LOG2E, liA[nt].x);
            accS[nt][1] = fmaf(accS[nt][1], SCL8_LOG2E, liA[nt].y);
            accS[nt][2] = fmaf(accS[nt][2], SCL8_LOG2E, liB[nt].x);
            accS[nt][3] = fmaf(accS[nt][3], SCL8_LOG2E, liB[nt].y);
        }

        // ---- online softmax (base-2) ----
        float mt0 = -CUDART_INF_F, mt1 = -CUDART_INF_F;
        #pragma unroll
        for (int nt = 0; nt < 8; nt++) {
            mt0 = fmaxf(mt0, fmaxf(accS[nt][0], accS[nt][1]));
            mt1 = fmaxf(mt1, fmaxf(accS[nt][2], accS[nt][3]));
        }
        mt0 = fmaxf(mt0, __shfl_xor_sync(0xffffffffu, mt0, 1));
        mt0 = fmaxf(mt0, __shfl_xor_sync(0xffffffffu, mt0, 2));
        mt1 = fmaxf(mt1, __shfl_xor_sync(0xffffffffu, mt1, 1));
        mt1 = fmaxf(mt1, __shfl_xor_sync(0xffffffffu, mt1, 2));
        float mn0 = fmaxf(mi0, mt0), mn1 = fmaxf(mi1, mt1);
        float al0 = ex2f(mi0 - mn0), al1 = ex2f(mi1 - mn1);
        mi0 = mn0; mi1 = mn1;

        // p' = 2^10 * p (exact power-of-2 scale; cancels in O/l)
        uint32_t pa[4][4];
        float rs0 = 0.f, rs1 = 0.f;
        #pragma unroll
        for (int nt = 0; nt < 8; nt++) {
            float p0 = ex2f(accS[nt][0] - mn0 + 10.f);
            float p1 = ex2f(accS[nt][1] - mn0 + 10.f);
            float p2 = ex2f(accS[nt][2] - mn1 + 10.f);
            float p3 = ex2f(accS[nt][3] - mn1 + 10.f);
            rs0 += p0 + p1; rs1 += p2 + p3;
            int kt = nt >> 1, off = (nt & 1) * 2;
            pa[kt][off]     = hf2pk(p1, p0);
            pa[kt][off + 1] = hf2pk(p3, p2);
        }
        rs0 += __shfl_xor_sync(0xffffffffu, rs0, 1);
        rs0 += __shfl_xor_sync(0xffffffffu, rs0, 2);
        rs1 += __shfl_xor_sync(0xffffffffu, rs1, 1);
        rs1 += __shfl_xor_sync(0xffffffffu, rs1, 2);
        ls0 = ls0 * al0 + rs0;
        ls1 = ls1 * al1 + rs1;

        #pragma unroll
        for (int nt = 0; nt < 8; nt++) {
            accO[nt][0] *= al0; accO[nt][1] *= al0;
            accO[nt][2] *= al1; accO[nt][3] *= al1;
        }

        // ---- O += P V (fp16: P single, V hi/lo) ----
        #pragma unroll
        for (int kt = 0; kt < 4; kt++) {
            uint32_t vh[4][4], vl[4][4];
            #pragma unroll
            for (int db = 0; db < 4; db++) {
                uint32_t ad = stV + (kt * 16 + (lane & 15)) * FP
                            + (db * 16 + (lane >> 4) * 8) * 2;
                LDSM4T(vh[db], ad);
                LDSM4T(vl[db], ad + 64 * FP);
            }
            #pragma unroll
            for (int db = 0; db < 4; db++) {
                uint32_t bh0[2] = {vh[db][0], vh[db][1]}, bh1[2] = {vh[db][2], vh[db][3]};
                uint32_t bl0[2] = {vl[db][0], vl[db][1]}, bl1[2] = {vl[db][2], vl[db][3]};
                MMA_F16(accO[2*db],   pa[kt], bh0);
                MMA_F16(accO[2*db],   pa[kt], bl0);
                MMA_F16(accO[2*db+1], pa[kt], bh1);
                MMA_F16(accO[2*db+1], pa[kt], bl1);
            }
        }
        __syncthreads();
    }

    // ---- epilogue: O/l + bout (2^10 scale cancels) ----
    const float inv0 = 1.f / ls0, inv1 = 1.f / ls1;
    #pragma unroll
    for (int nt = 0; nt < 8; nt++) {
        const int col = grp * DH + nt * 8 + 2 * th;
        float2 bo = *(const float2*)(bout + col);
        const int row = n0 + wid * 16 + g;
        *(float2*)(out + (size_t)row * CDIM + col) =
            make_float2(accO[nt][0] * inv0 + bo.x, accO[nt][1] * inv0 + bo.y);
        *(float2*)(out + (size_t)(row + 8) * CDIM + col) =
            make_float2(accO[nt][2] * inv1 + bo.x, accO[nt][3] * inv1 + bo.y);
    }
}

// ============================================================================
// launch
// ============================================================================
extern "C" void kernel_launch(void* const* d_in, const int* in_sizes, int n_in,
                              void* d_out, int out_size) {
    const float* in_x = (const float*)d_in[0];
    const float* rois = (const float*)d_in[1];
    const float* W0   = (const float*)d_in[2];
    const float* b0   = (const float*)d_in[3];
    const float* W1   = (const float*)d_in[4];
    const float* b1   = (const float*)d_in[5];
    const float* Wout = (const float*)d_in[6];
    const float* bout = (const float*)d_in[7];
    float* out = (float*)d_out;

    void *pA0h,*pA0l,*pA1h,*pA1l,*pA2h,*pA2l,*pW0h,*pW0l,*pW1h,*pW1l,*pWph,*pWpl;
    void *pXh,*pXl,*pVh,*pVl,*pLI;
    cudaGetSymbolAddress(&pA0h, g_A0h); cudaGetSymbolAddress(&pA0l, g_A0l);
    cudaGetSymbolAddress(&pA1h, g_A1h); cudaGetSymbolAddress(&pA1l, g_A1l);
    cudaGetSymbolAddress(&pA2h, g_A2h); cudaGetSymbolAddress(&pA2l, g_A2l);
    cudaGetSymbolAddress(&pW0h, g_W0h); cudaGetSymbolAddress(&pW0l, g_W0l);
    cudaGetSymbolAddress(&pW1h, g_W1h); cudaGetSymbolAddress(&pW1l, g_W1l);
    cudaGetSymbolAddress(&pWph, g_Wph); cudaGetSymbolAddress(&pWpl, g_Wpl);
    cudaGetSymbolAddress(&pXh, g_Xh);   cudaGetSymbolAddress(&pXl, g_Xl);
    cudaGetSymbolAddress(&pVh, g_Vh);   cudaGetSymbolAddress(&pVl, g_Vl);
    cudaGetSymbolAddress(&pLI, g_LI);

    // one merged split launch (7168 blocks covers both activations + 3 weights)
    split_all<<<7168, 256>>>(in_x, W0, W1, Wout,
                             (__nv_bfloat16*)pA0h, (__nv_bfloat16*)pA0l,
                             (__nv_bfloat16*)pA2h, (__nv_bfloat16*)pA2l,
                             (__nv_bfloat16*)pW0h, (__nv_bfloat16*)pW0l,
                             (__nv_bfloat16*)pW1h, (__nv_bfloat16*)pW1l,
                             (__nv_bfloat16*)pWph, (__nv_bfloat16*)pWpl);

    logiou_kernel<<<(NROI * NROI) / 256, 256>>>(rois, (float*)pLI);

    cudaFuncSetAttribute(gemm_tc<0>, cudaFuncAttributeMaxDynamicSharedMemorySize, GEMM_SMEM);
    cudaFuncSetAttribute(gemm_tc<1>, cudaFuncAttributeMaxDynamicSharedMemorySize, GEMM_SMEM);
    cudaFuncSetAttribute(gemm_tc<2>, cudaFuncAttributeMaxDynamicSharedMemorySize, GEMM_SMEM);
    dim3 ggrid(CDIM / 128, NROI / 128);

    // GEMM0: relu(relu(in_x)@W0^T + b0) -> A1 (bf16 split)
    gemm_tc<0><<<ggrid, 256, GEMM_SMEM>>>((__nv_bfloat16*)pA0h, (__nv_bfloat16*)pA0l,
                                          (__nv_bfloat16*)pW0h, (__nv_bfloat16*)pW0l,
                                          b0, (__nv_bfloat16*)pA1h, (__nv_bfloat16*)pA1l);
    // GEMM1: relu(H0)@W1^T + b1 -> X (bf16 split, flash Q/K)
    gemm_tc<1><<<ggrid, 256, GEMM_SMEM>>>((__nv_bfloat16*)pA1h, (__nv_bfloat16*)pA1l,
                                          (__nv_bfloat16*)pW1h, (__nv_bfloat16*)pW1l,
                                          b1, (__nv_bfloat16*)pXh, (__nv_bfloat16*)pXl);
    // GEMM2: in_x@Wout^T -> V (fp16 split, flash V)
    gemm_tc<2><<<ggrid, 256, GEMM_SMEM>>>((__nv_bfloat16*)pA2h, (__nv_bfloat16*)pA2l,
                                          (__nv_bfloat16*)pWph, (__nv_bfloat16*)pWpl,
                                          nullptr, (__nv_bfloat16*)pVh, (__nv_bfloat16*)pVl);

    // HMMA flash attention
    cudaFuncSetAttribute(flash_hmma, cudaFuncAttributeMaxDynamicSharedMemorySize, FLASH_SMEM);
    flash_hmma<<<dim3(NROI / 128, GRP), 256, FLASH_SMEM>>>(
        (__nv_bfloat16*)pXh, (__nv_bfloat16*)pXl,
        (__nv_bfloat16*)pVh, (__nv_bfloat16*)pVl,
        (float*)pLI, bout, out);
}